// round 3
// baseline (speedup 1.0000x reference)
#include <cuda_runtime.h>
#include <cuda_bf16.h>

#define N_NODES 100000
#define D 128
#define E_MAX 1600000
#define SCAN_CHUNK 1024
#define SCAN_NB ((N_NODES + SCAN_CHUNK - 1) / SCAN_CHUNK)   // 98

// ---------------- scratch (static device globals; no allocation) ----------------
__device__ float g_h0[(size_t)N_NODES * D];   // h0, later reused for h2
__device__ float g_h1[(size_t)N_NODES * D];
__device__ float g_agg[(size_t)N_NODES * D];
__device__ int   g_hist[N_NODES];
__device__ int   g_rowptr[N_NODES + 1];
__device__ int   g_cursor[N_NODES];
__device__ int   g_csr[E_MAX];
__device__ int   g_blocksums[SCAN_NB];

// packed f32x2 helpers (sm_100+)
__device__ __forceinline__ void fma_f32x2(unsigned long long& d,
                                          unsigned long long a,
                                          unsigned long long b) {
    asm("fma.rn.f32x2 %0, %1, %2, %0;" : "+l"(d) : "l"(a), "l"(b));
}
__device__ __forceinline__ unsigned long long dup_f32(float a) {
    unsigned long long r;
    asm("mov.b64 %0, {%1, %1};" : "=l"(r) : "f"(a));
    return r;
}
__device__ __forceinline__ float2 unpack_f32x2(unsigned long long v) {
    float2 r;
    asm("mov.b64 {%0, %1}, %2;" : "=f"(r.x), "=f"(r.y) : "l"(v));
    return r;
}

// ---------------- zero int ----------------
__global__ void zero_int_kernel(int* __restrict__ p, int n) {
    int i = blockIdx.x * blockDim.x + threadIdx.x;
    int stride = gridDim.x * blockDim.x;
    for (; i < n; i += stride) p[i] = 0;
}

// ---------------- histogram of dst ----------------
__global__ void hist_kernel(const int* __restrict__ dst, int* __restrict__ hist, int E) {
    int i = blockIdx.x * blockDim.x + threadIdx.x;
    if (i >= E) return;
    atomicAdd(&hist[dst[i]], 1);
}

// ---------------- scan phase 1: per-block sums ----------------
__global__ void scan1_kernel(const int* __restrict__ hist, int* __restrict__ blocksums) {
    __shared__ int sh[256];
    int t = threadIdx.x;
    int base = blockIdx.x * SCAN_CHUNK + t * 4;
    int s = 0;
#pragma unroll
    for (int j = 0; j < 4; j++) {
        int idx = base + j;
        if (idx < N_NODES) s += hist[idx];
    }
    sh[t] = s;
    __syncthreads();
    for (int o = 128; o > 0; o >>= 1) {
        if (t < o) sh[t] += sh[t + o];
        __syncthreads();
    }
    if (t == 0) blocksums[blockIdx.x] = sh[0];
}

// ---------------- scan phase 2: exclusive scan of block sums (tiny) ----------------
__global__ void scan2_kernel(int* __restrict__ blocksums, int nb, int* __restrict__ rowptr) {
    if (threadIdx.x == 0 && blockIdx.x == 0) {
        int run = 0;
        for (int i = 0; i < nb; i++) {
            int v = blocksums[i];
            blocksums[i] = run;
            run += v;
        }
        rowptr[N_NODES] = run;
    }
}

// ---------------- scan phase 3: local exclusive scan + write rowptr & cursor ----------------
__global__ void scan3_kernel(const int* __restrict__ hist, const int* __restrict__ blocksums,
                             int* __restrict__ rowptr, int* __restrict__ cursor) {
    __shared__ int sh[256];
    int t = threadIdx.x;
    int base = blockIdx.x * SCAN_CHUNK + t * 4;
    int v[4];
    int s = 0;
#pragma unroll
    for (int j = 0; j < 4; j++) {
        int idx = base + j;
        v[j] = (idx < N_NODES) ? hist[idx] : 0;
        s += v[j];
    }
    sh[t] = s;
    __syncthreads();
    int val = s;
    for (int o = 1; o < 256; o <<= 1) {
        int other = (t >= o) ? sh[t - o] : 0;
        __syncthreads();
        val += other;
        sh[t] = val;
        __syncthreads();
    }
    int texcl = val - s;
    int off = blocksums[blockIdx.x] + texcl;
#pragma unroll
    for (int j = 0; j < 4; j++) {
        int idx = base + j;
        if (idx < N_NODES) {
            rowptr[idx] = off;
            cursor[idx] = off;
        }
        off += v[j];
    }
}

// ---------------- fill CSR ----------------
__global__ void fill_kernel(const int* __restrict__ src, const int* __restrict__ dst,
                            int* __restrict__ cursor, int* __restrict__ csr, int E) {
    int i = blockIdx.x * blockDim.x + threadIdx.x;
    if (i >= E) return;
    int p = atomicAdd(&cursor[dst[i]], 1);
    csr[p] = src[i];
}

// ---------------- gather + mean: one warp per dst node ----------------
__global__ void __launch_bounds__(256) gather_mean_kernel(
    const float* __restrict__ h, const int* __restrict__ csr,
    const int* __restrict__ rowptr, float* __restrict__ agg)
{
    int gw = (blockIdx.x * blockDim.x + threadIdx.x) >> 5;
    int lane = threadIdx.x & 31;
    if (gw >= N_NODES) return;
    int n0 = rowptr[gw];
    int n1 = rowptr[gw + 1];
    float4 acc = make_float4(0.f, 0.f, 0.f, 0.f);
    for (int base = n0; base < n1; base += 32) {
        int idx = base + lane;
        int sj = (idx < n1) ? csr[idx] : 0;
        int cnt = min(32, n1 - base);
        for (int t = 0; t < cnt; t++) {
            int s = __shfl_sync(0xFFFFFFFFu, sj, t);
            float4 v = ((const float4*)(h + (size_t)s * 128))[lane];
            acc.x += v.x; acc.y += v.y; acc.z += v.z; acc.w += v.w;
        }
    }
    float inv = (n1 > n0) ? 1.0f / (float)(n1 - n0) : 0.0f;
    acc.x *= inv; acc.y *= inv; acc.z *= inv; acc.w *= inv;
    ((float4*)(agg + (size_t)gw * 128))[lane] = acc;
}

// ---------------- single GEMM: C = act(A @ W + bias), f32x2 inner ----------------
template<int RELU>
__global__ void __launch_bounds__(256) gemm_kernel(
    const float* __restrict__ A, const float* __restrict__ W,
    const float* __restrict__ bias, float* __restrict__ C, int M)
{
    __shared__ float Ast[32][128];
    __shared__ float Ws[32][128];

    const int tid = threadIdx.x;
    const int tx = tid & 15;
    const int ty = tid >> 4;
    const int block_m = blockIdx.x * 128;

    unsigned long long acc[8][4];   // pairs along n
#pragma unroll
    for (int i = 0; i < 8; i++)
#pragma unroll
        for (int j = 0; j < 4; j++) acc[i][j] = 0ull;

    for (int k0 = 0; k0 < 128; k0 += 32) {
#pragma unroll
        for (int it = 0; it < 4; it++) {
            int i = tid + it * 256;
            int m = i >> 3;
            int k4 = (i & 7) << 2;
            int gm = block_m + m;
            float4 v = make_float4(0.f, 0.f, 0.f, 0.f);
            if (gm < M) v = *(const float4*)(A + (size_t)gm * 128 + k0 + k4);
            Ast[k4 + 0][m] = v.x; Ast[k4 + 1][m] = v.y;
            Ast[k4 + 2][m] = v.z; Ast[k4 + 3][m] = v.w;
        }
#pragma unroll
        for (int it = 0; it < 4; it++) {
            int i = tid + it * 256;
            int k = i >> 5;
            int n4 = (i & 31) << 2;
            *(float4*)&Ws[k][n4] = *(const float4*)(W + (size_t)(k0 + k) * 128 + n4);
        }
        __syncthreads();
#pragma unroll 8
        for (int k = 0; k < 32; k++) {
            float a[8];
            unsigned long long bp[4];
            *(float4*)&a[0] = *(float4*)&Ast[k][ty * 8];
            *(float4*)&a[4] = *(float4*)&Ast[k][ty * 8 + 4];
            ulonglong2 t0 = *(ulonglong2*)&Ws[k][tx * 8];
            ulonglong2 t1 = *(ulonglong2*)&Ws[k][tx * 8 + 4];
            bp[0] = t0.x; bp[1] = t0.y; bp[2] = t1.x; bp[3] = t1.y;
#pragma unroll
            for (int i = 0; i < 8; i++) {
                unsigned long long ad = dup_f32(a[i]);
#pragma unroll
                for (int j = 0; j < 4; j++)
                    fma_f32x2(acc[i][j], ad, bp[j]);
            }
        }
        __syncthreads();
    }

    const int gn = tx * 8;
#pragma unroll
    for (int i = 0; i < 8; i++) {
        int gm = block_m + ty * 8 + i;
        if (gm >= M) continue;
        float4* cp = (float4*)(C + (size_t)gm * 128 + gn);
#pragma unroll
        for (int jj = 0; jj < 2; jj++) {
            float2 p0 = unpack_f32x2(acc[i][jj * 2 + 0]);
            float2 p1 = unpack_f32x2(acc[i][jj * 2 + 1]);
            float4 r = make_float4(p0.x, p0.y, p1.x, p1.y);
            const float4 bb = *(const float4*)(bias + gn + jj * 4);
            r.x += bb.x; r.y += bb.y; r.z += bb.z; r.w += bb.w;
            if (RELU) {
                r.x = fmaxf(r.x, 0.f); r.y = fmaxf(r.y, 0.f);
                r.z = fmaxf(r.z, 0.f); r.w = fmaxf(r.w, 0.f);
            }
            cp[jj] = r;
        }
    }
}

// ---------------- fused dual GEMM: C = act(A1 @ W1 + A2 @ W2 + bias), f32x2 inner ----------------
template<int RELU>
__global__ void __launch_bounds__(256) dual_gemm_kernel(
    const float* __restrict__ A1, const float* __restrict__ W1,
    const float* __restrict__ A2, const float* __restrict__ W2,
    const float* __restrict__ bias, float* __restrict__ C, int M)
{
    __shared__ float Ast1[16][128];
    __shared__ float Ast2[16][128];
    __shared__ float Ws1[16][128];
    __shared__ float Ws2[16][128];

    const int tid = threadIdx.x;
    const int tx = tid & 15;
    const int ty = tid >> 4;
    const int block_m = blockIdx.x * 128;

    unsigned long long acc[8][4];
#pragma unroll
    for (int i = 0; i < 8; i++)
#pragma unroll
        for (int j = 0; j < 4; j++) acc[i][j] = 0ull;

    for (int k0 = 0; k0 < 128; k0 += 16) {
#pragma unroll
        for (int it = 0; it < 2; it++) {
            int i = tid + it * 256;
            int m = i >> 2;
            int k4 = (i & 3) << 2;
            int gm = block_m + m;
            float4 v1 = make_float4(0.f, 0.f, 0.f, 0.f);
            float4 v2 = make_float4(0.f, 0.f, 0.f, 0.f);
            if (gm < M) {
                v1 = *(const float4*)(A1 + (size_t)gm * 128 + k0 + k4);
                v2 = *(const float4*)(A2 + (size_t)gm * 128 + k0 + k4);
            }
            Ast1[k4 + 0][m] = v1.x; Ast1[k4 + 1][m] = v1.y;
            Ast1[k4 + 2][m] = v1.z; Ast1[k4 + 3][m] = v1.w;
            Ast2[k4 + 0][m] = v2.x; Ast2[k4 + 1][m] = v2.y;
            Ast2[k4 + 2][m] = v2.z; Ast2[k4 + 3][m] = v2.w;
        }
#pragma unroll
        for (int it = 0; it < 2; it++) {
            int i = tid + it * 256;
            int k = i >> 5;
            int n4 = (i & 31) << 2;
            *(float4*)&Ws1[k][n4] = *(const float4*)(W1 + (size_t)(k0 + k) * 128 + n4);
            *(float4*)&Ws2[k][n4] = *(const float4*)(W2 + (size_t)(k0 + k) * 128 + n4);
        }
        __syncthreads();
#pragma unroll
        for (int k = 0; k < 16; k++) {
            float a1[8], a2[8];
            unsigned long long bp1[4], bp2[4];
            *(float4*)&a1[0] = *(float4*)&Ast1[k][ty * 8];
            *(float4*)&a1[4] = *(float4*)&Ast1[k][ty * 8 + 4];
            *(float4*)&a2[0] = *(float4*)&Ast2[k][ty * 8];
            *(float4*)&a2[4] = *(float4*)&Ast2[k][ty * 8 + 4];
            {
                ulonglong2 t0 = *(ulonglong2*)&Ws1[k][tx * 8];
                ulonglong2 t1 = *(ulonglong2*)&Ws1[k][tx * 8 + 4];
                bp1[0] = t0.x; bp1[1] = t0.y; bp1[2] = t1.x; bp1[3] = t1.y;
            }
            {
                ulonglong2 t0 = *(ulonglong2*)&Ws2[k][tx * 8];
                ulonglong2 t1 = *(ulonglong2*)&Ws2[k][tx * 8 + 4];
                bp2[0] = t0.x; bp2[1] = t0.y; bp2[2] = t1.x; bp2[3] = t1.y;
            }
#pragma unroll
            for (int i = 0; i < 8; i++) {
                unsigned long long ad1 = dup_f32(a1[i]);
                unsigned long long ad2 = dup_f32(a2[i]);
#pragma unroll
                for (int j = 0; j < 4; j++) {
                    fma_f32x2(acc[i][j], ad1, bp1[j]);
                    fma_f32x2(acc[i][j], ad2, bp2[j]);
                }
            }
        }
        __syncthreads();
    }

    const int gn = tx * 8;
#pragma unroll
    for (int i = 0; i < 8; i++) {
        int gm = block_m + ty * 8 + i;
        if (gm >= M) continue;
        float4* cp = (float4*)(C + (size_t)gm * 128 + gn);
#pragma unroll
        for (int jj = 0; jj < 2; jj++) {
            float2 p0 = unpack_f32x2(acc[i][jj * 2 + 0]);
            float2 p1 = unpack_f32x2(acc[i][jj * 2 + 1]);
            float4 r = make_float4(p0.x, p0.y, p1.x, p1.y);
            const float4 bb = *(const float4*)(bias + gn + jj * 4);
            r.x += bb.x; r.y += bb.y; r.z += bb.z; r.w += bb.w;
            if (RELU) {
                r.x = fmaxf(r.x, 0.f); r.y = fmaxf(r.y, 0.f);
                r.z = fmaxf(r.z, 0.f); r.w = fmaxf(r.w, 0.f);
            }
            cp[jj] = r;
        }
    }
}

// ---------------- edge scores: one warp per pair, both sets in one launch ----------------
__global__ void score_kernel(const float* __restrict__ h,
                             const int* __restrict__ pa, const int* __restrict__ pb, int P,
                             const int* __restrict__ na, const int* __restrict__ nb, int Q,
                             float* __restrict__ out)
{
    int gw = (blockIdx.x * blockDim.x + threadIdx.x) >> 5;
    int lane = threadIdx.x & 31;
    if (gw >= P + Q) return;
    int ia, ib;
    if (gw < P) { ia = pa[gw]; ib = pb[gw]; }
    else        { ia = na[gw - P]; ib = nb[gw - P]; }
    float4 va = ((const float4*)(h + (size_t)ia * 128))[lane];
    float4 vb = ((const float4*)(h + (size_t)ib * 128))[lane];
    float s = va.x * vb.x + va.y * vb.y + va.z * vb.z + va.w * vb.w;
#pragma unroll
    for (int o = 16; o > 0; o >>= 1) s += __shfl_xor_sync(0xFFFFFFFFu, s, o);
    if (lane == 0) out[gw] = s;
}

// ---------------- host-side CSR build + gather sequence ----------------
static void build_csr_and_gather(const float* h, const int* src, const int* dst, int E,
                                 int* hist, int* rowptr, int* cursor, int* csr,
                                 int* blocksums, float* agg)
{
    zero_int_kernel<<<128, 256>>>(hist, N_NODES);
    hist_kernel<<<(E + 255) / 256, 256>>>(dst, hist, E);
    scan1_kernel<<<SCAN_NB, 256>>>(hist, blocksums);
    scan2_kernel<<<1, 32>>>(blocksums, SCAN_NB, rowptr);
    scan3_kernel<<<SCAN_NB, 256>>>(hist, blocksums, rowptr, cursor);
    fill_kernel<<<(E + 255) / 256, 256>>>(src, dst, cursor, csr, E);
    gather_mean_kernel<<<(N_NODES * 32 + 255) / 256, 256>>>(h, csr, rowptr, agg);
}

extern "C" void kernel_launch(void* const* d_in, const int* in_sizes, int n_in,
                              void* d_out, int out_size)
{
    const float* feat    = (const float*)d_in[0];
    const int*   e0s     = (const int*)d_in[1];
    const int*   e0d     = (const int*)d_in[2];
    const int*   e1s     = (const int*)d_in[3];
    const int*   e1d     = (const int*)d_in[4];
    const int*   ps      = (const int*)d_in[5];
    const int*   pd      = (const int*)d_in[6];
    const int*   ns      = (const int*)d_in[7];
    const int*   nd      = (const int*)d_in[8];
    const float* w_proj  = (const float*)d_in[9];
    const float* b_proj  = (const float*)d_in[10];
    const float* w_self1 = (const float*)d_in[11];
    const float* w_neigh1= (const float*)d_in[12];
    const float* b1      = (const float*)d_in[13];
    const float* w_self2 = (const float*)d_in[14];
    const float* w_neigh2= (const float*)d_in[15];
    const float* b2      = (const float*)d_in[16];

    const int E0 = in_sizes[1];
    const int E1 = in_sizes[3];
    const int P  = in_sizes[5];
    const int Q  = in_sizes[7];
    float* out = (float*)d_out;

    float *h0, *h1, *agg;
    int *hist, *rowptr, *cursor, *csr, *blocksums;
    cudaGetSymbolAddress((void**)&h0,  g_h0);
    cudaGetSymbolAddress((void**)&h1,  g_h1);
    cudaGetSymbolAddress((void**)&agg, g_agg);
    cudaGetSymbolAddress((void**)&hist, g_hist);
    cudaGetSymbolAddress((void**)&rowptr, g_rowptr);
    cudaGetSymbolAddress((void**)&cursor, g_cursor);
    cudaGetSymbolAddress((void**)&csr, g_csr);
    cudaGetSymbolAddress((void**)&blocksums, g_blocksums);

    const int gemm_grid = (N_NODES + 127) / 128;

    // h0 = relu(feat @ w_proj + b_proj)
    gemm_kernel<1><<<gemm_grid, 256>>>(feat, w_proj, b_proj, h0, N_NODES);

    // ---- layer 1 ----
    build_csr_and_gather(h0, e0s, e0d, E0, hist, rowptr, cursor, csr, blocksums, agg);
    dual_gemm_kernel<1><<<gemm_grid, 256>>>(h0, w_self1, agg, w_neigh1, b1, h1, N_NODES);

    // ---- layer 2 ----
    build_csr_and_gather(h1, e1s, e1d, E1, hist, rowptr, cursor, csr, blocksums, agg);
    dual_gemm_kernel<0><<<gemm_grid, 256>>>(h1, w_self2, agg, w_neigh2, b2, h0, N_NODES);

    // ---- scores ----
    score_kernel<<<(P + Q + 7) / 8, 256>>>(h0, ps, pd, P, ns, nd, Q, out);
}

// round 5
// speedup vs baseline: 1.5539x; 1.5539x over previous
#include <cuda_runtime.h>
#include <cuda_bf16.h>
#include <cstdint>

#define N_NODES 100000
#define D 128
#define E_MAX 1600000
#define SCAN_CHUNK 1024
#define SCAN_NB ((N_NODES + SCAN_CHUNK - 1) / SCAN_CHUNK)   // 98

// ---------------- scratch (static device globals; no allocation) ----------------
__device__ float g_h0[(size_t)N_NODES * D];
__device__ float g_h1[(size_t)N_NODES * D];
__device__ float g_agg[(size_t)N_NODES * D];
__device__ int   g_hist[N_NODES];
__device__ int   g_rowptr[N_NODES + 1];
__device__ int   g_cursor[N_NODES];
__device__ int   g_csr[E_MAX];
__device__ int   g_blocksums[SCAN_NB];
// pre-split weights: [5 matrices][hi/lo][128*128] bf16, transposed (B[n][k]=W[k][n]),
// stored in the swizzled physical layout used in shared memory.
__device__ __nv_bfloat16 g_wsw[5][2][128 * 128];

// ================= helpers =================
__device__ __forceinline__ uint32_t smem_u32(const void* p) {
    uint32_t a;
    asm("{ .reg .u64 t; cvta.to.shared.u64 t, %1; cvt.u32.u64 %0, t; }" : "=r"(a) : "l"(p));
    return a;
}
// pack two f32 -> bf16x2 (x -> low 16 bits / first in memory)
__device__ __forceinline__ uint32_t pack_bf16x2(float x, float y) {
    uint32_t r;
    asm("cvt.rn.bf16x2.f32 %0, %1, %2;" : "=r"(r) : "f"(y), "f"(x));
    return r;
}
// physical byte offset of element (row r, col k) in a [128][128] bf16 operand tile:
// 256B rows, 16B chunks XOR-swizzled by (r & 7) for conflict-free ldmatrix.
__device__ __forceinline__ uint32_t tile_off(int r, int k) {
    return (uint32_t)r * 256u + (uint32_t)(((k >> 3) ^ (r & 7)) << 4) + (uint32_t)(k & 7) * 2u;
}
__device__ __forceinline__ uint32_t chunk_off(int r, int kc) {   // 16B-chunk granularity
    return (uint32_t)r * 256u + (uint32_t)((kc ^ (r & 7)) << 4);
}

__device__ __forceinline__ void ldsm_x4(uint32_t* f, uint32_t addr) {
    asm volatile("ldmatrix.sync.aligned.m8n8.x4.shared.b16 {%0,%1,%2,%3}, [%4];"
                 : "=r"(f[0]), "=r"(f[1]), "=r"(f[2]), "=r"(f[3]) : "r"(addr));
}
__device__ __forceinline__ void ldsm_x2(uint32_t* f, uint32_t addr) {
    asm volatile("ldmatrix.sync.aligned.m8n8.x2.shared.b16 {%0,%1}, [%2];"
                 : "=r"(f[0]), "=r"(f[1]) : "r"(addr));
}
__device__ __forceinline__ void mma_bf16(float* c, const uint32_t* a, const uint32_t* b) {
    asm volatile("mma.sync.aligned.m16n8k16.row.col.f32.bf16.bf16.f32 "
                 "{%0,%1,%2,%3}, {%4,%5,%6,%7}, {%8,%9}, {%0,%1,%2,%3};"
                 : "+f"(c[0]), "+f"(c[1]), "+f"(c[2]), "+f"(c[3])
                 : "r"(a[0]), "r"(a[1]), "r"(a[2]), "r"(a[3]), "r"(b[0]), "r"(b[1]));
}

// ================= weight prep: W[k][n] fp32 -> B[n][k] bf16 hi/lo, swizzled =================
__global__ void prep_w_kernel(const float* __restrict__ W,
                              __nv_bfloat16* __restrict__ hi, __nv_bfloat16* __restrict__ lo) {
    int e = blockIdx.x * 256 + threadIdx.x;       // 0..16383
    int n = e >> 7, k = e & 127;
    float v = W[k * 128 + n];
    float h = __bfloat162float(__float2bfloat16_rn(v));
    uint32_t sw = tile_off(n, k);
    *(__nv_bfloat16*)((char*)hi + sw) = __float2bfloat16_rn(h);
    *(__nv_bfloat16*)((char*)lo + sw) = __float2bfloat16_rn(v - h);
}

// ================= split-bf16 GEMM via mma.sync =================
// block: 128x128x128 tile, 256 threads = 8 warps (2 warp-rows x 4 warp-cols),
// warp tile 64(m) x 32(n). smem: A hi/lo + B hi/lo, 32KB each.
#define SA_HI 0
#define SA_LO 32768
#define SB_HI 65536
#define SB_LO 98304
#define SMEM_MMA 131072

__device__ __forceinline__ void stage_A(const float* __restrict__ A, char* smem,
                                        int block_m, int M, int tid) {
#pragma unroll
    for (int it = 0; it < 8; it++) {
        int chunk = tid + it * 256;        // 0..2047 (16B chunks)
        int r = chunk >> 4;                // 0..127
        int kc = chunk & 15;               // 0..15
        int gm = block_m + r;
        float4 v0 = make_float4(0.f, 0.f, 0.f, 0.f);
        float4 v1 = v0;
        if (gm < M) {
            const float4* gp = (const float4*)(A + (size_t)gm * 128 + kc * 8);
            v0 = gp[0]; v1 = gp[1];
        }
        float h0 = __bfloat162float(__float2bfloat16_rn(v0.x));
        float h1 = __bfloat162float(__float2bfloat16_rn(v0.y));
        float h2 = __bfloat162float(__float2bfloat16_rn(v0.z));
        float h3 = __bfloat162float(__float2bfloat16_rn(v0.w));
        float h4 = __bfloat162float(__float2bfloat16_rn(v1.x));
        float h5 = __bfloat162float(__float2bfloat16_rn(v1.y));
        float h6 = __bfloat162float(__float2bfloat16_rn(v1.z));
        float h7 = __bfloat162float(__float2bfloat16_rn(v1.w));
        uint4 hp, lp;
        hp.x = pack_bf16x2(h0, h1);        hp.y = pack_bf16x2(h2, h3);
        hp.z = pack_bf16x2(h4, h5);        hp.w = pack_bf16x2(h6, h7);
        lp.x = pack_bf16x2(v0.x - h0, v0.y - h1);
        lp.y = pack_bf16x2(v0.z - h2, v0.w - h3);
        lp.z = pack_bf16x2(v1.x - h4, v1.y - h5);
        lp.w = pack_bf16x2(v1.z - h6, v1.w - h7);
        uint32_t sw = chunk_off(r, kc);
        *(uint4*)(smem + SA_HI + sw) = hp;
        *(uint4*)(smem + SA_LO + sw) = lp;
    }
}

__device__ __forceinline__ void stage_B(const __nv_bfloat16* __restrict__ Bhi,
                                        const __nv_bfloat16* __restrict__ Blo,
                                        char* smem, int tid) {
#pragma unroll
    for (int it = 0; it < 8; it++) {
        int off = (tid + it * 256) * 16;   // 32KB
        *(uint4*)(smem + SB_HI + off) = *(const uint4*)((const char*)Bhi + off);
        *(uint4*)(smem + SB_LO + off) = *(const uint4*)((const char*)Blo + off);
    }
}

// one full K=128 accumulation pass over staged smem
__device__ __forceinline__ void mma_pass(uint32_t sb, int wid, int lane, float acc[4][4][4]) {
    const int m_base = (wid & 1) * 64;
    const int n_base = (wid >> 1) * 32;
    const int ra = (lane & 15);            // A ldmatrix row within 16
    const int kca_add = (lane >> 4);       // A chunk select
    const int nb = (lane & 7);             // B ldmatrix row within 8
    const int kcb_add = ((lane >> 3) & 1); // B chunk select
#pragma unroll
    for (int kk = 0; kk < 8; kk++) {
        uint32_t ah[4][4], al[4][4], bh[4][2], bl[4][2];
#pragma unroll
        for (int im = 0; im < 4; im++) {
            int r = m_base + im * 16 + ra;
            uint32_t a = sb + chunk_off(r, 2 * kk + kca_add);
            ldsm_x4(ah[im], a + SA_HI);
            ldsm_x4(al[im], a + SA_LO);
        }
#pragma unroll
        for (int in = 0; in < 4; in++) {
            int n = n_base + in * 8 + nb;
            uint32_t a = sb + chunk_off(n, 2 * kk + kcb_add);
            ldsm_x2(bh[in], a + SB_HI);
            ldsm_x2(bl[in], a + SB_LO);
        }
#pragma unroll
        for (int im = 0; im < 4; im++)
#pragma unroll
            for (int in = 0; in < 4; in++) {
                mma_bf16(acc[im][in], ah[im], bh[in]);
                mma_bf16(acc[im][in], ah[im], bl[in]);
                mma_bf16(acc[im][in], al[im], bh[in]);
            }
    }
}

template<int DUAL, int RELU>
__global__ void __launch_bounds__(256, 1) gemm_mma_kernel(
    const float* __restrict__ A1,
    const __nv_bfloat16* __restrict__ B1hi, const __nv_bfloat16* __restrict__ B1lo,
    const float* __restrict__ A2,
    const __nv_bfloat16* __restrict__ B2hi, const __nv_bfloat16* __restrict__ B2lo,
    const float* __restrict__ bias, float* __restrict__ C, int M)
{
    extern __shared__ __align__(128) char smem[];
    const uint32_t sb = smem_u32(smem);
    const int tid = threadIdx.x;
    const int wid = tid >> 5;
    const int lane = tid & 31;
    const int block_m = blockIdx.x * 128;

    float acc[4][4][4];
#pragma unroll
    for (int im = 0; im < 4; im++)
#pragma unroll
        for (int in = 0; in < 4; in++)
#pragma unroll
            for (int q = 0; q < 4; q++) acc[im][in][q] = 0.0f;

    stage_A(A1, smem, block_m, M, tid);
    stage_B(B1hi, B1lo, smem, tid);
    __syncthreads();
    mma_pass(sb, wid, lane, acc);

    if (DUAL) {
        __syncthreads();                    // everyone done reading stage 1
        stage_A(A2, smem, block_m, M, tid);
        stage_B(B2hi, B2lo, smem, tid);
        __syncthreads();
        mma_pass(sb, wid, lane, acc);
    }

    // epilogue: acc[im][in] fragment -> rows (t>>2, t>>2+8), cols 2*(t&3)+{0,1}
    const int m_base = block_m + (wid & 1) * 64;
    const int n_base = (wid >> 1) * 32;
    const int rq = lane >> 2;
    const int cq = (lane & 3) * 2;
#pragma unroll
    for (int im = 0; im < 4; im++) {
#pragma unroll
        for (int in = 0; in < 4; in++) {
            int gn = n_base + in * 8 + cq;
            float bx = bias[gn], by = bias[gn + 1];
#pragma unroll
            for (int half = 0; half < 2; half++) {
                int gm = m_base + im * 16 + rq + half * 8;
                if (gm >= M) continue;
                float x = acc[im][in][half * 2 + 0] + bx;
                float y = acc[im][in][half * 2 + 1] + by;
                if (RELU) { x = fmaxf(x, 0.f); y = fmaxf(y, 0.f); }
                *(float2*)(C + (size_t)gm * 128 + gn) = make_float2(x, y);
            }
        }
    }
}

// ================= graph aggregation (proven R2 versions) =================
__global__ void zero_int_kernel(int* __restrict__ p, int n) {
    int i = blockIdx.x * blockDim.x + threadIdx.x;
    int stride = gridDim.x * blockDim.x;
    for (; i < n; i += stride) p[i] = 0;
}

__global__ void hist_kernel(const int* __restrict__ dst, int* __restrict__ hist, int E) {
    int i = blockIdx.x * blockDim.x + threadIdx.x;
    if (i >= E) return;
    atomicAdd(&hist[dst[i]], 1);
}

__global__ void scan1_kernel(const int* __restrict__ hist, int* __restrict__ blocksums) {
    __shared__ int sh[256];
    int t = threadIdx.x;
    int base = blockIdx.x * SCAN_CHUNK + t * 4;
    int s = 0;
#pragma unroll
    for (int j = 0; j < 4; j++) {
        int idx = base + j;
        if (idx < N_NODES) s += hist[idx];
    }
    sh[t] = s;
    __syncthreads();
    for (int o = 128; o > 0; o >>= 1) {
        if (t < o) sh[t] += sh[t + o];
        __syncthreads();
    }
    if (t == 0) blocksums[blockIdx.x] = sh[0];
}

__global__ void scan2_kernel(int* __restrict__ blocksums, int nb, int* __restrict__ rowptr) {
    if (threadIdx.x == 0 && blockIdx.x == 0) {
        int run = 0;
        for (int i = 0; i < nb; i++) {
            int v = blocksums[i];
            blocksums[i] = run;
            run += v;
        }
        rowptr[N_NODES] = run;
    }
}

__global__ void scan3_kernel(const int* __restrict__ hist, const int* __restrict__ blocksums,
                             int* __restrict__ rowptr, int* __restrict__ cursor) {
    __shared__ int sh[256];
    int t = threadIdx.x;
    int base = blockIdx.x * SCAN_CHUNK + t * 4;
    int v[4];
    int s = 0;
#pragma unroll
    for (int j = 0; j < 4; j++) {
        int idx = base + j;
        v[j] = (idx < N_NODES) ? hist[idx] : 0;
        s += v[j];
    }
    sh[t] = s;
    __syncthreads();
    int val = s;
    for (int o = 1; o < 256; o <<= 1) {
        int other = (t >= o) ? sh[t - o] : 0;
        __syncthreads();
        val += other;
        sh[t] = val;
        __syncthreads();
    }
    int texcl = val - s;
    int off = blocksums[blockIdx.x] + texcl;
#pragma unroll
    for (int j = 0; j < 4; j++) {
        int idx = base + j;
        if (idx < N_NODES) {
            rowptr[idx] = off;
            cursor[idx] = off;
        }
        off += v[j];
    }
}

__global__ void fill_kernel(const int* __restrict__ src, const int* __restrict__ dst,
                            int* __restrict__ cursor, int* __restrict__ csr, int E) {
    int i = blockIdx.x * blockDim.x + threadIdx.x;
    if (i >= E) return;
    int p = atomicAdd(&cursor[dst[i]], 1);
    csr[p] = src[i];
}

__global__ void __launch_bounds__(256) gather_mean_kernel(
    const float* __restrict__ h, const int* __restrict__ csr,
    const int* __restrict__ rowptr, float* __restrict__ agg)
{
    int gw = (blockIdx.x * blockDim.x + threadIdx.x) >> 5;
    int lane = threadIdx.x & 31;
    if (gw >= N_NODES) return;
    int n0 = rowptr[gw];
    int n1 = rowptr[gw + 1];
    float4 acc = make_float4(0.f, 0.f, 0.f, 0.f);
    for (int base = n0; base < n1; base += 32) {
        int idx = base + lane;
        int sj = (idx < n1) ? csr[idx] : 0;
        int cnt = min(32, n1 - base);
        for (int t = 0; t < cnt; t++) {
            int s = __shfl_sync(0xFFFFFFFFu, sj, t);
            float4 v = ((const float4*)(h + (size_t)s * 128))[lane];
            acc.x += v.x; acc.y += v.y; acc.z += v.z; acc.w += v.w;
        }
    }
    float inv = (n1 > n0) ? 1.0f / (float)(n1 - n0) : 0.0f;
    acc.x *= inv; acc.y *= inv; acc.z *= inv; acc.w *= inv;
    ((float4*)(agg + (size_t)gw * 128))[lane] = acc;
}

__global__ void score_kernel(const float* __restrict__ h,
                             const int* __restrict__ pa, const int* __restrict__ pb, int P,
                             const int* __restrict__ na, const int* __restrict__ nb, int Q,
                             float* __restrict__ out)
{
    int gw = (blockIdx.x * blockDim.x + threadIdx.x) >> 5;
    int lane = threadIdx.x & 31;
    if (gw >= P + Q) return;
    int ia, ib;
    if (gw < P) { ia = pa[gw]; ib = pb[gw]; }
    else        { ia = na[gw - P]; ib = nb[gw - P]; }
    float4 va = ((const float4*)(h + (size_t)ia * 128))[lane];
    float4 vb = ((const float4*)(h + (size_t)ib * 128))[lane];
    float s = va.x * vb.x + va.y * vb.y + va.z * vb.z + va.w * vb.w;
#pragma unroll
    for (int o = 16; o > 0; o >>= 1) s += __shfl_xor_sync(0xFFFFFFFFu, s, o);
    if (lane == 0) out[gw] = s;
}

static void build_csr_and_gather(const float* h, const int* src, const int* dst, int E,
                                 int* hist, int* rowptr, int* cursor, int* csr,
                                 int* blocksums, float* agg)
{
    zero_int_kernel<<<128, 256>>>(hist, N_NODES);
    hist_kernel<<<(E + 255) / 256, 256>>>(dst, hist, E);
    scan1_kernel<<<SCAN_NB, 256>>>(hist, blocksums);
    scan2_kernel<<<1, 32>>>(blocksums, SCAN_NB, rowptr);
    scan3_kernel<<<SCAN_NB, 256>>>(hist, blocksums, rowptr, cursor);
    fill_kernel<<<(E + 255) / 256, 256>>>(src, dst, cursor, csr, E);
    gather_mean_kernel<<<(N_NODES * 32 + 255) / 256, 256>>>(h, csr, rowptr, agg);
}

extern "C" void kernel_launch(void* const* d_in, const int* in_sizes, int n_in,
                              void* d_out, int out_size)
{
    const float* feat    = (const float*)d_in[0];
    const int*   e0s     = (const int*)d_in[1];
    const int*   e0d     = (const int*)d_in[2];
    const int*   e1s     = (const int*)d_in[3];
    const int*   e1d     = (const int*)d_in[4];
    const int*   ps      = (const int*)d_in[5];
    const int*   pd      = (const int*)d_in[6];
    const int*   ns      = (const int*)d_in[7];
    const int*   nd      = (const int*)d_in[8];
    const float* w_proj  = (const float*)d_in[9];
    const float* b_proj  = (const float*)d_in[10];
    const float* w_self1 = (const float*)d_in[11];
    const float* w_neigh1= (const float*)d_in[12];
    const float* b1      = (const float*)d_in[13];
    const float* w_self2 = (const float*)d_in[14];
    const float* w_neigh2= (const float*)d_in[15];
    const float* b2      = (const float*)d_in[16];

    const int E0 = in_sizes[1];
    const int E1 = in_sizes[3];
    const int P  = in_sizes[5];
    const int Q  = in_sizes[7];
    float* out = (float*)d_out;

    float *h0, *h1, *agg;
    int *hist, *rowptr, *cursor, *csr, *blocksums;
    __nv_bfloat16* wsw;
    cudaGetSymbolAddress((void**)&h0,  g_h0);
    cudaGetSymbolAddress((void**)&h1,  g_h1);
    cudaGetSymbolAddress((void**)&agg, g_agg);
    cudaGetSymbolAddress((void**)&hist, g_hist);
    cudaGetSymbolAddress((void**)&rowptr, g_rowptr);
    cudaGetSymbolAddress((void**)&cursor, g_cursor);
    cudaGetSymbolAddress((void**)&csr, g_csr);
    cudaGetSymbolAddress((void**)&blocksums, g_blocksums);
    cudaGetSymbolAddress((void**)&wsw, g_wsw);
    auto W = [&](int m, int part) { return wsw + ((size_t)m * 2 + part) * 128 * 128; };

    cudaFuncSetAttribute(gemm_mma_kernel<0, 1>, cudaFuncAttributeMaxDynamicSharedMemorySize, SMEM_MMA);
    cudaFuncSetAttribute(gemm_mma_kernel<1, 1>, cudaFuncAttributeMaxDynamicSharedMemorySize, SMEM_MMA);
    cudaFuncSetAttribute(gemm_mma_kernel<1, 0>, cudaFuncAttributeMaxDynamicSharedMemorySize, SMEM_MMA);

    // weight prep (tiny)
    prep_w_kernel<<<64, 256>>>(w_proj,   W(0, 0), W(0, 1));
    prep_w_kernel<<<64, 256>>>(w_self1,  W(1, 0), W(1, 1));
    prep_w_kernel<<<64, 256>>>(w_neigh1, W(2, 0), W(2, 1));
    prep_w_kernel<<<64, 256>>>(w_self2,  W(3, 0), W(3, 1));
    prep_w_kernel<<<64, 256>>>(w_neigh2, W(4, 0), W(4, 1));

    const int gemm_grid = (N_NODES + 127) / 128;   // 782

    // h0 = relu(feat @ w_proj + b_proj)
    gemm_mma_kernel<0, 1><<<gemm_grid, 256, SMEM_MMA>>>(
        feat, W(0, 0), W(0, 1), nullptr, nullptr, nullptr, b_proj, h0, N_NODES);

    // ---- layer 1 ----
    build_csr_and_gather(h0, e0s, e0d, E0, hist, rowptr, cursor, csr, blocksums, agg);
    gemm_mma_kernel<1, 1><<<gemm_grid, 256, SMEM_MMA>>>(
        h0, W(1, 0), W(1, 1), agg, W(2, 0), W(2, 1), b1, h1, N_NODES);

    // ---- layer 2 ----
    build_csr_and_gather(h1, e1s, e1d, E1, hist, rowptr, cursor, csr, blocksums, agg);
    gemm_mma_kernel<1, 0><<<gemm_grid, 256, SMEM_MMA>>>(
        h1, W(3, 0), W(3, 1), agg, W(4, 0), W(4, 1), b2, h0, N_NODES);

    // ---- scores ----
    score_kernel<<<(P + Q + 7) / 8, 256>>>(h0, ps, pd, P, ns, nd, Q, out);
}